// round 8
// baseline (speedup 1.0000x reference)
#include <cuda_runtime.h>
#include <cuda_bf16.h>
#include <cstdint>

#define N_NODES 100000
#define N_EDGES 200000
#define N_GRAPHS 64
#define F_IN 5
#define HID 768
#define EMB 512
#define N_LAYERS 16
#define HSQ ((size_t)HID * HID)

// GEMM tiling: 128x128x32, 256 threads, 2-stage pipeline, 3 CTAs/SM
#define BM 128
#define BN 128
#define BK 32
#define NT (HID / BK)       // 24 k-iterations
#define SA_H 0
#define SA_L 8192
#define SB_H 16384
#define SB_L 24576
#define STAGE 32768
#define GSMEM (2 * STAGE)   // 65536

#define SWZ(o) ((o) ^ ((((uint32_t)(o)) >> 3) & 0x70))

#define NELEM ((size_t)N_NODES * HID)
#define NB 98               // ceil(N_NODES / 1024)

// ---------------- scratch (allocation-free: __device__ globals) ----------------
__device__ __nv_bfloat16 g_hh[NELEM], g_hl[NELEM];   // node features
__device__ __nv_bfloat16 g_ah[NELEM], g_al[NELEM];   // aggregated
__device__ __nv_bfloat16 g_zh[NELEM], g_zl[NELEM];   // MLP hidden
__device__ float g_pooled[N_GRAPHS * HID];
__device__ int   g_start[N_GRAPHS + 1];
// CSR
__device__ int g_off[N_NODES + 1];
__device__ int g_fill[N_NODES];
__device__ int g_csr[N_EDGES];
__device__ int g_bsum[NB];
__device__ int g_bpre[NB];
// transposed, split-precision weights: [32][n][k]
__device__ __nv_bfloat16 g_wth[32 * HSQ];
__device__ __nv_bfloat16 g_wtl[32 * HSQ];

// ---------------- helpers ----------------
__device__ __forceinline__ uint32_t smem_u32(const void* p) {
    uint32_t a;
    asm("{ .reg .u64 t; cvta.to.shared.u64 t, %1; cvt.u32.u64 %0, t; }" : "=r"(a) : "l"(p));
    return a;
}
__device__ __forceinline__ void cp16z(uint32_t dst, const void* src, bool ok) {
    int sz = ok ? 16 : 0;
    asm volatile("cp.async.cg.shared.global [%0], [%1], 16, %2;"
                 :: "r"(dst), "l"(src), "r"(sz));
}
__device__ __forceinline__ void ldx4(uint32_t r[4], uint32_t addr) {
    asm volatile("ldmatrix.sync.aligned.m8n8.x4.shared.b16 {%0,%1,%2,%3}, [%4];"
                 : "=r"(r[0]), "=r"(r[1]), "=r"(r[2]), "=r"(r[3]) : "r"(addr));
}
__device__ __forceinline__ void mma16816(float d[4], const uint32_t a[4], const uint32_t b[2]) {
    asm volatile(
        "mma.sync.aligned.m16n8k16.row.col.f32.bf16.bf16.f32 "
        "{%0,%1,%2,%3}, {%4,%5,%6,%7}, {%8,%9}, {%0,%1,%2,%3};"
        : "+f"(d[0]), "+f"(d[1]), "+f"(d[2]), "+f"(d[3])
        : "r"(a[0]), "r"(a[1]), "r"(a[2]), "r"(a[3]), "r"(b[0]), "r"(b[1]));
}
__device__ __forceinline__ void split2(float v0, float v1, uint32_t& h, uint32_t& l) {
    __nv_bfloat162 h2 = __floats2bfloat162_rn(v0, v1);
    float2 f = __bfloat1622float2(h2);
    __nv_bfloat162 l2 = __floats2bfloat162_rn(v0 - f.x, v1 - f.y);
    h = *(uint32_t*)&h2;
    l = *(uint32_t*)&l2;
}
__device__ __forceinline__ float2 join2(uint32_t h, uint32_t l) {
    float2 fh = __bfloat1622float2(*(__nv_bfloat162*)&h);
    float2 fl = __bfloat1622float2(*(__nv_bfloat162*)&l);
    return make_float2(fh.x + fl.x, fh.y + fl.y);
}

// ---------------- weight transpose + bf16 hi/lo split ----------------
__global__ void wconv_kernel(const float* __restrict__ W1, const float* __restrict__ W2) {
    int m = blockIdx.z;
    const float* W = (m < 16) ? (W1 + (size_t)m * HSQ) : (W2 + (size_t)(m - 16) * HSQ);
    __shared__ float t[32][33];
    int k0 = blockIdx.y * 32, n0 = blockIdx.x * 32;
    for (int i = threadIdx.y; i < 32; i += 8)
        t[i][threadIdx.x] = W[(size_t)(k0 + i) * HID + n0 + threadIdx.x];
    __syncthreads();
    for (int i = threadIdx.y; i < 32; i += 8) {
        float v = t[threadIdx.x][i];
        __nv_bfloat16 h = __float2bfloat16(v);
        __nv_bfloat16 l = __float2bfloat16(v - __bfloat162float(h));
        size_t o = (size_t)m * HSQ + (size_t)(n0 + i) * HID + k0 + threadIdx.x;
        g_wth[o] = h;
        g_wtl[o] = l;
    }
}

// ---------------- CSR build ----------------
__global__ void zero_fill() {
    int i = blockIdx.x * blockDim.x + threadIdx.x;
    if (i < N_NODES) g_fill[i] = 0;
}
__global__ void count_kernel(const int* __restrict__ dst) {
    int e = blockIdx.x * blockDim.x + threadIdx.x;
    if (e < N_EDGES) atomicAdd(&g_fill[dst[e]], 1);
}
// fast scan: block partial sums -> 1-block scan -> per-block offsets
__global__ void bsum_kernel() {
    int b = blockIdx.x;
    int i = b * 1024 + threadIdx.x;
    int v = (i < N_NODES) ? g_fill[i] : 0;
    __shared__ int s[32];
    int w = threadIdx.x >> 5, l = threadIdx.x & 31;
#pragma unroll
    for (int o = 16; o; o >>= 1) v += __shfl_down_sync(0xFFFFFFFFu, v, o);
    if (l == 0) s[w] = v;
    __syncthreads();
    if (w == 0) {
        int x = s[l];
#pragma unroll
        for (int o = 16; o; o >>= 1) x += __shfl_down_sync(0xFFFFFFFFu, x, o);
        if (l == 0) g_bsum[b] = x;
    }
}
__global__ void bscan_kernel() {
    __shared__ int s[128];
    int t = threadIdx.x;
    int v = (t < NB) ? g_bsum[t] : 0;
    s[t] = v;
    __syncthreads();
    for (int d = 1; d < 128; d <<= 1) {
        int x = (t >= d) ? s[t - d] : 0;
        __syncthreads();
        s[t] += x;
        __syncthreads();
    }
    if (t < NB) g_bpre[t] = s[t] - v;   // exclusive
}
__global__ void offs_kernel() {
    __shared__ int s[1024];
    int b = blockIdx.x, t = threadIdx.x;
    int i = b * 1024 + t;
    int v = (i < N_NODES) ? g_fill[i] : 0;
    s[t] = v;
    __syncthreads();
    for (int d = 1; d < 1024; d <<= 1) {
        int x = (t >= d) ? s[t - d] : 0;
        __syncthreads();
        s[t] += x;
        __syncthreads();
    }
    if (i < N_NODES) {
        g_off[i] = g_bpre[b] + s[t] - v;
        g_fill[i] = 0;
    }
    if (b == 0 && t == 0) g_off[N_NODES] = N_EDGES;
}
__global__ void fill_kernel(const int* __restrict__ src, const int* __restrict__ dst) {
    int e = blockIdx.x * blockDim.x + threadIdx.x;
    if (e >= N_EDGES) return;
    int d = dst[e];
    int pos = g_off[d] + atomicAdd(&g_fill[d], 1);
    g_csr[pos] = src[e];
}

// ---------------- CSR gather: agg[n] = h[n] + sum_{j->n} h[j]  (hi/lo planes) ----------------
__global__ void gather_kernel() {
    int n = blockIdx.x;
    int c = threadIdx.x;  // 0..191
    const uint2* hh = (const uint2*)g_hh;
    const uint2* hl = (const uint2*)g_hl;
    size_t idx = (size_t)n * 192 + c;
    uint2 vh = hh[idx], vl = hl[idx];
    float2 a01 = join2(vh.x, vl.x);
    float2 a23 = join2(vh.y, vl.y);
    int lo = g_off[n], hi = g_off[n + 1];
    int j = lo;
    for (; j + 1 < hi; j += 2) {   // unroll 2: two independent row streams
        size_t s0 = (size_t)g_csr[j] * 192 + c;
        size_t s1 = (size_t)g_csr[j + 1] * 192 + c;
        uint2 wh0 = hh[s0], wl0 = hl[s0];
        uint2 wh1 = hh[s1], wl1 = hl[s1];
        float2 b01 = join2(wh0.x, wl0.x);
        float2 b23 = join2(wh0.y, wl0.y);
        float2 c01 = join2(wh1.x, wl1.x);
        float2 c23 = join2(wh1.y, wl1.y);
        a01.x += b01.x + c01.x; a01.y += b01.y + c01.y;
        a23.x += b23.x + c23.x; a23.y += b23.y + c23.y;
    }
    if (j < hi) {
        size_t si = (size_t)g_csr[j] * 192 + c;
        uint2 wh = hh[si], wl = hl[si];
        float2 b01 = join2(wh.x, wl.x);
        float2 b23 = join2(wh.y, wl.y);
        a01.x += b01.x; a01.y += b01.y;
        a23.x += b23.x; a23.y += b23.y;
    }
    uint2 oh, ol;
    split2(a01.x, a01.y, oh.x, ol.x);
    split2(a23.x, a23.y, oh.y, ol.y);
    ((uint2*)g_ah)[idx] = oh;
    ((uint2*)g_al)[idx] = ol;
}

// ---------------- stage loader: 4 bf16 tiles via cp.async, swizzled 64B rows ----------------
__device__ __forceinline__ void load_stage(uint32_t st,
                                           const __nv_bfloat16* __restrict__ Ah,
                                           const __nv_bfloat16* __restrict__ Al,
                                           const __nv_bfloat16* __restrict__ Bh,
                                           const __nv_bfloat16* __restrict__ Bl,
                                           int bm, int bn, int k0, int tid) {
#pragma unroll
    for (int i = 0; i < 2; i++) {
        int id = tid + 256 * i;
        int r = id >> 2, q = id & 3;
        uint32_t off = SWZ((uint32_t)(r * 64 + q * 16));
        size_t ao = (size_t)(bm + r) * HID + k0 + q * 8;
        bool aok = (bm + r) < N_NODES;
        cp16z(st + SA_H + off, Ah + ao, aok);
        cp16z(st + SA_L + off, Al + ao, aok);
        size_t bo = (size_t)(bn + r) * HID + k0 + q * 8;
        cp16z(st + SB_H + off, Bh + bo, true);
        cp16z(st + SB_L + off, Bl + bo, true);
    }
    asm volatile("cp.async.commit_group;" ::: "memory");
}

// ---------------- GEMM: C = relu(A @ Bt^T + bias); bf16 hi/lo planes ----------------
__global__ void __launch_bounds__(256, 3)
gemm_mma(const __nv_bfloat16* __restrict__ Ah, const __nv_bfloat16* __restrict__ Al,
         const __nv_bfloat16* __restrict__ Bh, const __nv_bfloat16* __restrict__ Bl,
         const float* __restrict__ bias,
         __nv_bfloat16* __restrict__ Ch, __nv_bfloat16* __restrict__ Cl)
{
    extern __shared__ char smem[];
    uint32_t sb = smem_u32(smem);
    int tid = threadIdx.x;
    int lane = tid & 31, wid = tid >> 5;
    int wm = wid >> 2;   // 0..1
    int wn = wid & 3;    // 0..3
    int bn = blockIdx.x * BN;
    int bm = blockIdx.y * BM;

    uint32_t oa0 = (uint32_t)((wm * 64 + (lane & 15)) * 64 + ((lane >> 4) << 4));
    uint32_t ob0 = (uint32_t)((wn * 32 + (lane & 7) + (((lane >> 4) & 1) << 3)) * 64
                              + (((lane >> 3) & 1) << 4));

    float d[4][4][4];
#pragma unroll
    for (int i = 0; i < 4; i++)
#pragma unroll
        for (int j = 0; j < 4; j++)
#pragma unroll
            for (int k = 0; k < 4; k++) d[i][j][k] = 0.f;

    load_stage(sb, Ah, Al, Bh, Bl, bm, bn, 0, tid);

    for (int t = 0; t < NT; t++) {
        uint32_t cur = sb + (uint32_t)(t & 1) * STAGE;
        uint32_t nxt = sb + (uint32_t)((t + 1) & 1) * STAGE;
        asm volatile("cp.async.wait_group 0;" ::: "memory");
        __syncthreads();
        if (t + 1 < NT)
            load_stage(nxt, Ah, Al, Bh, Bl, bm, bn, (t + 1) * BK, tid);

#pragma unroll
        for (int ks = 0; ks < 2; ks++) {
            uint32_t bh[4][2], bl[4][2];
#pragma unroll
            for (int np = 0; np < 2; np++) {
                uint32_t o = SWZ(ob0 + (uint32_t)(np * 1024 + ks * 32));
                uint32_t adr = cur + SB_H + o;
                uint32_t r4[4];
                ldx4(r4, adr);
                bh[2 * np][0] = r4[0]; bh[2 * np][1] = r4[1];
                bh[2 * np + 1][0] = r4[2]; bh[2 * np + 1][1] = r4[3];
                ldx4(r4, adr + (SB_L - SB_H));
                bl[2 * np][0] = r4[0]; bl[2 * np][1] = r4[1];
                bl[2 * np + 1][0] = r4[2]; bl[2 * np + 1][1] = r4[3];
            }
#pragma unroll
            for (int half = 0; half < 2; half++) {
                uint32_t ah[2][4], al[2][4];
#pragma unroll
                for (int m2 = 0; m2 < 2; m2++) {
                    int mf = half * 2 + m2;
                    uint32_t o = SWZ(oa0 + (uint32_t)(mf * 1024 + ks * 32));
                    uint32_t adr = cur + SA_H + o;
                    ldx4(ah[m2], adr);
                    ldx4(al[m2], adr + (SA_L - SA_H));
                }
#pragma unroll
                for (int m2 = 0; m2 < 2; m2++)
#pragma unroll
                    for (int nf = 0; nf < 4; nf++)
                        mma16816(d[half * 2 + m2][nf], ah[m2], bh[nf]);
#pragma unroll
                for (int m2 = 0; m2 < 2; m2++)
#pragma unroll
                    for (int nf = 0; nf < 4; nf++)
                        mma16816(d[half * 2 + m2][nf], ah[m2], bl[nf]);
#pragma unroll
                for (int m2 = 0; m2 < 2; m2++)
#pragma unroll
                    for (int nf = 0; nf < 4; nf++)
                        mma16816(d[half * 2 + m2][nf], al[m2], bh[nf]);
            }
        }
    }

    // epilogue: bias + relu, split to hi/lo bf16 planes
    int g = lane >> 2, tq = lane & 3;
#pragma unroll
    for (int mf = 0; mf < 4; mf++) {
        int row0 = bm + wm * 64 + mf * 16 + g;
        int row1 = row0 + 8;
#pragma unroll
        for (int nf = 0; nf < 4; nf++) {
            int col = bn + wn * 32 + nf * 8 + tq * 2;
            float b0 = __ldg(bias + col), b1 = __ldg(bias + col + 1);
            if (row0 < N_NODES) {
                float v0 = fmaxf(d[mf][nf][0] + b0, 0.f);
                float v1 = fmaxf(d[mf][nf][1] + b1, 0.f);
                uint32_t h, l;
                split2(v0, v1, h, l);
                *(uint32_t*)(Ch + (size_t)row0 * HID + col) = h;
                *(uint32_t*)(Cl + (size_t)row0 * HID + col) = l;
            }
            if (row1 < N_NODES) {
                float v0 = fmaxf(d[mf][nf][2] + b0, 0.f);
                float v1 = fmaxf(d[mf][nf][3] + b1, 0.f);
                uint32_t h, l;
                split2(v0, v1, h, l);
                *(uint32_t*)(Ch + (size_t)row1 * HID + col) = h;
                *(uint32_t*)(Cl + (size_t)row1 * HID + col) = l;
            }
        }
    }
}

// ---------------- input projection -> hi/lo planes ----------------
__global__ void proj_kernel(const float* __restrict__ x,
                            const float* __restrict__ Wp,
                            const float* __restrict__ bp) {
    int n = blockIdx.x;
    int j = threadIdx.x;
    __shared__ float xs[F_IN];
    if (j < F_IN) xs[j] = x[n * F_IN + j];
    __syncthreads();
    float acc = bp[j];
#pragma unroll
    for (int k = 0; k < F_IN; ++k) acc += xs[k] * Wp[k * HID + j];
    __nv_bfloat16 h = __float2bfloat16(acc);
    __nv_bfloat16 l = __float2bfloat16(acc - __bfloat162float(h));
    g_hh[(size_t)n * HID + j] = h;
    g_hl[(size_t)n * HID + j] = l;
}

// ---------------- graph boundaries ----------------
__global__ void find_starts(const int* __restrict__ batch) {
    int g = threadIdx.x;
    if (g > N_GRAPHS) return;
    if (g == N_GRAPHS) { g_start[g] = N_NODES; return; }
    int lo = 0, hi = N_NODES;
    while (lo < hi) {
        int mid = (lo + hi) >> 1;
        if (batch[mid] < g) lo = mid + 1;
        else hi = mid;
    }
    g_start[g] = lo;
}

// ---------------- mean pool (reads hi/lo) ----------------
__global__ void pool_kernel() {
    int g = blockIdx.x;
    int f = blockIdx.y * 256 + threadIdx.x;
    int s = g_start[g], e = g_start[g + 1];
    float acc = 0.f;
    for (int r = s; r < e; ++r) {
        size_t i = (size_t)r * HID + f;
        acc += __bfloat162float(g_hh[i]) + __bfloat162float(g_hl[i]);
    }
    float cnt = (float)(e - s);
    g_pooled[g * HID + f] = acc / fmaxf(cnt, 1.f);
}

// ---------------- out = pooled @ Wf + bf ----------------
__global__ void final_kernel(const float* __restrict__ Wf, const float* __restrict__ bfv,
                             float* __restrict__ out) {
    int g = blockIdx.x;
    int e = threadIdx.x;
    __shared__ float p[HID];
    for (int i = threadIdx.x; i < HID; i += EMB) p[i] = g_pooled[g * HID + i];
    __syncthreads();
    float acc = bfv[e];
#pragma unroll 4
    for (int k = 0; k < HID; ++k) acc += p[k] * Wf[k * EMB + e];
    out[g * EMB + e] = acc;
}

// ---------------- launch ----------------
extern "C" void kernel_launch(void* const* d_in, const int* in_sizes, int n_in,
                              void* d_out, int out_size) {
    const float* x   = (const float*)d_in[0];
    const int*   ei  = (const int*)d_in[1];
    const int* batch = (const int*)d_in[2];
    const float* Wp  = (const float*)d_in[3];
    const float* bp  = (const float*)d_in[4];
    const float* W1  = (const float*)d_in[5];
    const float* b1  = (const float*)d_in[6];
    const float* W2  = (const float*)d_in[7];
    const float* b2  = (const float*)d_in[8];
    const float* Wf  = (const float*)d_in[9];
    const float* bf  = (const float*)d_in[10];
    float* out = (float*)d_out;

    const int* src = ei;
    const int* dst = ei + N_EDGES;

    __nv_bfloat16 *wth, *wtl, *hh, *hl, *ah, *al, *zh, *zl;
    cudaGetSymbolAddress((void**)&wth, g_wth);
    cudaGetSymbolAddress((void**)&wtl, g_wtl);
    cudaGetSymbolAddress((void**)&hh, g_hh);
    cudaGetSymbolAddress((void**)&hl, g_hl);
    cudaGetSymbolAddress((void**)&ah, g_ah);
    cudaGetSymbolAddress((void**)&al, g_al);
    cudaGetSymbolAddress((void**)&zh, g_zh);
    cudaGetSymbolAddress((void**)&zl, g_zl);

    cudaFuncSetAttribute(gemm_mma, cudaFuncAttributeMaxDynamicSharedMemorySize, GSMEM);

    // weight transpose + hi/lo split
    wconv_kernel<<<dim3(HID / 32, HID / 32, 32), dim3(32, 8)>>>(W1, W2);

    // CSR build (fast scan)
    zero_fill<<<(N_NODES + 255) / 256, 256>>>();
    count_kernel<<<(N_EDGES + 255) / 256, 256>>>(dst);
    bsum_kernel<<<NB, 1024>>>();
    bscan_kernel<<<1, 128>>>();
    offs_kernel<<<NB, 1024>>>();
    fill_kernel<<<(N_EDGES + 255) / 256, 256>>>(src, dst);

    proj_kernel<<<N_NODES, HID>>>(x, Wp, bp);

    dim3 ggrid(HID / BN, (N_NODES + BM - 1) / BM);   // (6, 782)
    for (int l = 0; l < N_LAYERS; ++l) {
        gather_kernel<<<N_NODES, HID / 4>>>();
        gemm_mma<<<ggrid, 256, GSMEM>>>(ah, al, wth + (size_t)l * HSQ,
                                        wtl + (size_t)l * HSQ, b1 + l * HID, zh, zl);
        gemm_mma<<<ggrid, 256, GSMEM>>>(zh, zl, wth + (size_t)(16 + l) * HSQ,
                                        wtl + (size_t)(16 + l) * HSQ, b2 + l * HID, hh, hl);
    }

    find_starts<<<1, N_GRAPHS + 1>>>(batch);
    pool_kernel<<<dim3(N_GRAPHS, HID / 256), 256>>>();
    final_kernel<<<N_GRAPHS, EMB>>>(Wf, bf, out);
}

// round 9
// speedup vs baseline: 1.9146x; 1.9146x over previous
#include <cuda_runtime.h>
#include <cuda_bf16.h>
#include <cstdint>

#define N_NODES 100000
#define N_EDGES 200000
#define N_GRAPHS 64
#define F_IN 5
#define HID 768
#define EMB 512
#define N_LAYERS 16
#define HSQ ((size_t)HID * HID)

// GEMM tiling: 128x128x32, 256 threads, 2 CTAs/SM, 3-stage swizzled pipeline
#define BM 128
#define BN 128
#define BK 32
#define NT (HID / BK)       // 24 k-iterations
#define SA_H 0
#define SA_L 8192
#define SB_H 16384
#define SB_L 24576
#define STAGE 32768
#define NSTG 3
#define GSMEM (NSTG * STAGE)   // 98304

#define SWZ(o) ((o) ^ ((((uint32_t)(o)) >> 3) & 0x70))

#define NELEM ((size_t)N_NODES * HID)
#define NB 98               // ceil(N_NODES / 1024)

// ---------------- scratch (allocation-free: __device__ globals) ----------------
__device__ __nv_bfloat16 g_hh[NELEM], g_hl[NELEM];   // node features
__device__ __nv_bfloat16 g_ah[NELEM], g_al[NELEM];   // aggregated
__device__ __nv_bfloat16 g_zh[NELEM], g_zl[NELEM];   // MLP hidden
__device__ float g_pooled[N_GRAPHS * HID];
__device__ int   g_start[N_GRAPHS + 1];
// CSR
__device__ int g_off[N_NODES + 1];
__device__ int g_fill[N_NODES];
__device__ int g_csr[N_EDGES];
__device__ int g_bsum[NB];
__device__ int g_bpre[NB];
// transposed, split-precision weights: [32][n][k]
__device__ __nv_bfloat16 g_wth[32 * HSQ];
__device__ __nv_bfloat16 g_wtl[32 * HSQ];

// ---------------- helpers ----------------
__device__ __forceinline__ uint32_t smem_u32(const void* p) {
    uint32_t a;
    asm("{ .reg .u64 t; cvta.to.shared.u64 t, %1; cvt.u32.u64 %0, t; }" : "=r"(a) : "l"(p));
    return a;
}
__device__ __forceinline__ void cp16z(uint32_t dst, const void* src, bool ok) {
    int sz = ok ? 16 : 0;
    asm volatile("cp.async.cg.shared.global [%0], [%1], 16, %2;"
                 :: "r"(dst), "l"(src), "r"(sz));
}
__device__ __forceinline__ void ldx4(uint32_t r[4], uint32_t addr) {
    asm volatile("ldmatrix.sync.aligned.m8n8.x4.shared.b16 {%0,%1,%2,%3}, [%4];"
                 : "=r"(r[0]), "=r"(r[1]), "=r"(r[2]), "=r"(r[3]) : "r"(addr));
}
__device__ __forceinline__ void mma16816(float d[4], const uint32_t a[4], const uint32_t b[2]) {
    asm volatile(
        "mma.sync.aligned.m16n8k16.row.col.f32.bf16.bf16.f32 "
        "{%0,%1,%2,%3}, {%4,%5,%6,%7}, {%8,%9}, {%0,%1,%2,%3};"
        : "+f"(d[0]), "+f"(d[1]), "+f"(d[2]), "+f"(d[3])
        : "r"(a[0]), "r"(a[1]), "r"(a[2]), "r"(a[3]), "r"(b[0]), "r"(b[1]));
}
__device__ __forceinline__ void split2(float v0, float v1, uint32_t& h, uint32_t& l) {
    __nv_bfloat162 h2 = __floats2bfloat162_rn(v0, v1);
    float2 f = __bfloat1622float2(h2);
    __nv_bfloat162 l2 = __floats2bfloat162_rn(v0 - f.x, v1 - f.y);
    h = *(uint32_t*)&h2;
    l = *(uint32_t*)&l2;
}
__device__ __forceinline__ float2 join2(uint32_t h, uint32_t l) {
    float2 fh = __bfloat1622float2(*(__nv_bfloat162*)&h);
    float2 fl = __bfloat1622float2(*(__nv_bfloat162*)&l);
    return make_float2(fh.x + fl.x, fh.y + fl.y);
}

// ---------------- weight transpose + bf16 hi/lo split ----------------
__global__ void wconv_kernel(const float* __restrict__ W1, const float* __restrict__ W2) {
    int m = blockIdx.z;
    const float* W = (m < 16) ? (W1 + (size_t)m * HSQ) : (W2 + (size_t)(m - 16) * HSQ);
    __shared__ float t[32][33];
    int k0 = blockIdx.y * 32, n0 = blockIdx.x * 32;
    for (int i = threadIdx.y; i < 32; i += 8)
        t[i][threadIdx.x] = W[(size_t)(k0 + i) * HID + n0 + threadIdx.x];
    __syncthreads();
    for (int i = threadIdx.y; i < 32; i += 8) {
        float v = t[threadIdx.x][i];
        __nv_bfloat16 h = __float2bfloat16(v);
        __nv_bfloat16 l = __float2bfloat16(v - __bfloat162float(h));
        size_t o = (size_t)m * HSQ + (size_t)(n0 + i) * HID + k0 + threadIdx.x;
        g_wth[o] = h;
        g_wtl[o] = l;
    }
}

// ---------------- CSR build ----------------
__global__ void zero_fill() {
    int i = blockIdx.x * blockDim.x + threadIdx.x;
    if (i < N_NODES) g_fill[i] = 0;
}
__global__ void count_kernel(const int* __restrict__ dst) {
    int e = blockIdx.x * blockDim.x + threadIdx.x;
    if (e < N_EDGES) atomicAdd(&g_fill[dst[e]], 1);
}
// fast scan: block partial sums -> 1-block scan -> per-block offsets
__global__ void bsum_kernel() {
    int b = blockIdx.x;
    int i = b * 1024 + threadIdx.x;
    int v = (i < N_NODES) ? g_fill[i] : 0;
    __shared__ int s[32];
    int w = threadIdx.x >> 5, l = threadIdx.x & 31;
#pragma unroll
    for (int o = 16; o; o >>= 1) v += __shfl_down_sync(0xFFFFFFFFu, v, o);
    if (l == 0) s[w] = v;
    __syncthreads();
    if (w == 0) {
        int x = s[l];
#pragma unroll
        for (int o = 16; o; o >>= 1) x += __shfl_down_sync(0xFFFFFFFFu, x, o);
        if (l == 0) g_bsum[b] = x;
    }
}
__global__ void bscan_kernel() {
    __shared__ int s[128];
    int t = threadIdx.x;
    int v = (t < NB) ? g_bsum[t] : 0;
    s[t] = v;
    __syncthreads();
    for (int d = 1; d < 128; d <<= 1) {
        int x = (t >= d) ? s[t - d] : 0;
        __syncthreads();
        s[t] += x;
        __syncthreads();
    }
    if (t < NB) g_bpre[t] = s[t] - v;   // exclusive
}
__global__ void offs_kernel() {
    __shared__ int s[1024];
    int b = blockIdx.x, t = threadIdx.x;
    int i = b * 1024 + t;
    int v = (i < N_NODES) ? g_fill[i] : 0;
    s[t] = v;
    __syncthreads();
    for (int d = 1; d < 1024; d <<= 1) {
        int x = (t >= d) ? s[t - d] : 0;
        __syncthreads();
        s[t] += x;
        __syncthreads();
    }
    if (i < N_NODES) {
        g_off[i] = g_bpre[b] + s[t] - v;
        g_fill[i] = 0;
    }
    if (b == 0 && t == 0) g_off[N_NODES] = N_EDGES;
}
__global__ void fill_kernel(const int* __restrict__ src, const int* __restrict__ dst) {
    int e = blockIdx.x * blockDim.x + threadIdx.x;
    if (e >= N_EDGES) return;
    int d = dst[e];
    int pos = g_off[d] + atomicAdd(&g_fill[d], 1);
    g_csr[pos] = src[e];
}

// ---------------- CSR gather: agg[n] = h[n] + sum_{j->n} h[j]  (hi/lo planes) ----------------
__global__ void gather_kernel() {
    int n = blockIdx.x;
    int c = threadIdx.x;  // 0..191
    const uint2* hh = (const uint2*)g_hh;
    const uint2* hl = (const uint2*)g_hl;
    size_t idx = (size_t)n * 192 + c;
    uint2 vh = hh[idx], vl = hl[idx];
    float2 a01 = join2(vh.x, vl.x);
    float2 a23 = join2(vh.y, vl.y);
    int lo = g_off[n], hi = g_off[n + 1];
    int j = lo;
    for (; j + 1 < hi; j += 2) {   // unroll 2: two independent row streams
        size_t s0 = (size_t)g_csr[j] * 192 + c;
        size_t s1 = (size_t)g_csr[j + 1] * 192 + c;
        uint2 wh0 = hh[s0], wl0 = hl[s0];
        uint2 wh1 = hh[s1], wl1 = hl[s1];
        float2 b01 = join2(wh0.x, wl0.x);
        float2 b23 = join2(wh0.y, wl0.y);
        float2 c01 = join2(wh1.x, wl1.x);
        float2 c23 = join2(wh1.y, wl1.y);
        a01.x += b01.x + c01.x; a01.y += b01.y + c01.y;
        a23.x += b23.x + c23.x; a23.y += b23.y + c23.y;
    }
    if (j < hi) {
        size_t si = (size_t)g_csr[j] * 192 + c;
        uint2 wh = hh[si], wl = hl[si];
        float2 b01 = join2(wh.x, wl.x);
        float2 b23 = join2(wh.y, wl.y);
        a01.x += b01.x; a01.y += b01.y;
        a23.x += b23.x; a23.y += b23.y;
    }
    uint2 oh, ol;
    split2(a01.x, a01.y, oh.x, ol.x);
    split2(a23.x, a23.y, oh.y, ol.y);
    ((uint2*)g_ah)[idx] = oh;
    ((uint2*)g_al)[idx] = ol;
}

// ---------------- stage loader: 4 bf16 tiles via cp.async, swizzled 64B rows ----------------
__device__ __forceinline__ void load_stage(uint32_t st,
                                           const __nv_bfloat16* __restrict__ Ah,
                                           const __nv_bfloat16* __restrict__ Al,
                                           const __nv_bfloat16* __restrict__ Bh,
                                           const __nv_bfloat16* __restrict__ Bl,
                                           int bm, int bn, int k0, int tid) {
#pragma unroll
    for (int i = 0; i < 2; i++) {
        int id = tid + 256 * i;
        int r = id >> 2, q = id & 3;           // r 0..127, q = 16B chunk of 64B row
        uint32_t off = SWZ((uint32_t)(r * 64 + q * 16));
        size_t ao = (size_t)(bm + r) * HID + k0 + q * 8;
        bool aok = (bm + r) < N_NODES;
        cp16z(st + SA_H + off, Ah + ao, aok);
        cp16z(st + SA_L + off, Al + ao, aok);
        size_t bo = (size_t)(bn + r) * HID + k0 + q * 8;
        cp16z(st + SB_H + off, Bh + bo, true);
        cp16z(st + SB_L + off, Bl + bo, true);
    }
    asm volatile("cp.async.commit_group;" ::: "memory");
}

// ---------------- GEMM: C = relu(A @ Bt^T + bias); bf16 hi/lo planes ----------------
__global__ void __launch_bounds__(256, 2)
gemm_mma(const __nv_bfloat16* __restrict__ Ah, const __nv_bfloat16* __restrict__ Al,
         const __nv_bfloat16* __restrict__ Bh, const __nv_bfloat16* __restrict__ Bl,
         const float* __restrict__ bias,
         __nv_bfloat16* __restrict__ Ch, __nv_bfloat16* __restrict__ Cl)
{
    extern __shared__ char smem[];
    uint32_t sb = smem_u32(smem);
    int tid = threadIdx.x;
    int lane = tid & 31, wid = tid >> 5;
    int wm = wid >> 2;   // 0..1
    int wn = wid & 3;    // 0..3
    int bn = blockIdx.x * BN;
    int bm = blockIdx.y * BM;

    // hoisted unswizzled base offsets (stage-relative)
    uint32_t oa0 = (uint32_t)((wm * 64 + (lane & 15)) * 64 + ((lane >> 4) << 4));
    uint32_t ob0 = (uint32_t)((wn * 32 + (lane & 7) + (((lane >> 4) & 1) << 3)) * 64
                              + (((lane >> 3) & 1) << 4));

    float d[4][4][4];
#pragma unroll
    for (int i = 0; i < 4; i++)
#pragma unroll
        for (int j = 0; j < 4; j++)
#pragma unroll
            for (int k = 0; k < 4; k++) d[i][j][k] = 0.f;

    load_stage(sb,         Ah, Al, Bh, Bl, bm, bn, 0,  tid);
    load_stage(sb + STAGE, Ah, Al, Bh, Bl, bm, bn, BK, tid);

    int slot = 0;                 // slot of stage t
    int lslot = 2;                // slot for stage t+2
    for (int t = 0; t < NT; t++) {
        if (t + 2 < NT) {
            asm volatile("cp.async.wait_group 1;" ::: "memory");
        } else {
            asm volatile("cp.async.wait_group 0;" ::: "memory");
        }
        __syncthreads();
        if (t + 2 < NT)
            load_stage(sb + (uint32_t)lslot * STAGE, Ah, Al, Bh, Bl, bm, bn, (t + 2) * BK, tid);
        uint32_t cur = sb + (uint32_t)slot * STAGE;
        if (++slot == NSTG) slot = 0;
        if (++lslot == NSTG) lslot = 0;

#pragma unroll
        for (int ks = 0; ks < 2; ks++) {
            uint32_t bh[4][2], bl[4][2];
#pragma unroll
            for (int np = 0; np < 2; np++) {
                uint32_t o = SWZ(ob0 + (uint32_t)(np * 1024 + ks * 32));
                uint32_t adr = cur + SB_H + o;
                uint32_t r4[4];
                ldx4(r4, adr);
                bh[2 * np][0] = r4[0]; bh[2 * np][1] = r4[1];
                bh[2 * np + 1][0] = r4[2]; bh[2 * np + 1][1] = r4[3];
                ldx4(r4, adr + (SB_L - SB_H));
                bl[2 * np][0] = r4[0]; bl[2 * np][1] = r4[1];
                bl[2 * np + 1][0] = r4[2]; bl[2 * np + 1][1] = r4[3];
            }
#pragma unroll
            for (int half = 0; half < 2; half++) {
                uint32_t ah[2][4], al[2][4];
#pragma unroll
                for (int m2 = 0; m2 < 2; m2++) {
                    int mf = half * 2 + m2;
                    uint32_t o = SWZ(oa0 + (uint32_t)(mf * 1024 + ks * 32));
                    uint32_t adr = cur + SA_H + o;
                    ldx4(ah[m2], adr);
                    ldx4(al[m2], adr + (SA_L - SA_H));
                }
#pragma unroll
                for (int m2 = 0; m2 < 2; m2++)
#pragma unroll
                    for (int nf = 0; nf < 4; nf++)
                        mma16816(d[half * 2 + m2][nf], ah[m2], bh[nf]);
#pragma unroll
                for (int m2 = 0; m2 < 2; m2++)
#pragma unroll
                    for (int nf = 0; nf < 4; nf++)
                        mma16816(d[half * 2 + m2][nf], ah[m2], bl[nf]);
#pragma unroll
                for (int m2 = 0; m2 < 2; m2++)
#pragma unroll
                    for (int nf = 0; nf < 4; nf++)
                        mma16816(d[half * 2 + m2][nf], al[m2], bh[nf]);
            }
        }
    }

    // epilogue: bias + relu, split to hi/lo bf16 planes
    int g = lane >> 2, tq = lane & 3;
#pragma unroll
    for (int mf = 0; mf < 4; mf++) {
        int row0 = bm + wm * 64 + mf * 16 + g;
        int row1 = row0 + 8;
#pragma unroll
        for (int nf = 0; nf < 4; nf++) {
            int col = bn + wn * 32 + nf * 8 + tq * 2;
            float b0 = __ldg(bias + col), b1 = __ldg(bias + col + 1);
            if (row0 < N_NODES) {
                float v0 = fmaxf(d[mf][nf][0] + b0, 0.f);
                float v1 = fmaxf(d[mf][nf][1] + b1, 0.f);
                uint32_t h, l;
                split2(v0, v1, h, l);
                *(uint32_t*)(Ch + (size_t)row0 * HID + col) = h;
                *(uint32_t*)(Cl + (size_t)row0 * HID + col) = l;
            }
            if (row1 < N_NODES) {
                float v0 = fmaxf(d[mf][nf][2] + b0, 0.f);
                float v1 = fmaxf(d[mf][nf][3] + b1, 0.f);
                uint32_t h, l;
                split2(v0, v1, h, l);
                *(uint32_t*)(Ch + (size_t)row1 * HID + col) = h;
                *(uint32_t*)(Cl + (size_t)row1 * HID + col) = l;
            }
        }
    }
}

// ---------------- input projection -> hi/lo planes ----------------
__global__ void proj_kernel(const float* __restrict__ x,
                            const float* __restrict__ Wp,
                            const float* __restrict__ bp) {
    int n = blockIdx.x;
    int j = threadIdx.x;
    __shared__ float xs[F_IN];
    if (j < F_IN) xs[j] = x[n * F_IN + j];
    __syncthreads();
    float acc = bp[j];
#pragma unroll
    for (int k = 0; k < F_IN; ++k) acc += xs[k] * Wp[k * HID + j];
    __nv_bfloat16 h = __float2bfloat16(acc);
    __nv_bfloat16 l = __float2bfloat16(acc - __bfloat162float(h));
    g_hh[(size_t)n * HID + j] = h;
    g_hl[(size_t)n * HID + j] = l;
}

// ---------------- graph boundaries ----------------
__global__ void find_starts(const int* __restrict__ batch) {
    int g = threadIdx.x;
    if (g > N_GRAPHS) return;
    if (g == N_GRAPHS) { g_start[g] = N_NODES; return; }
    int lo = 0, hi = N_NODES;
    while (lo < hi) {
        int mid = (lo + hi) >> 1;
        if (batch[mid] < g) lo = mid + 1;
        else hi = mid;
    }
    g_start[g] = lo;
}

// ---------------- mean pool (reads hi/lo) ----------------
__global__ void pool_kernel() {
    int g = blockIdx.x;
    int f = blockIdx.y * 256 + threadIdx.x;
    int s = g_start[g], e = g_start[g + 1];
    float acc = 0.f;
    for (int r = s; r < e; ++r) {
        size_t i = (size_t)r * HID + f;
        acc += __bfloat162float(g_hh[i]) + __bfloat162float(g_hl[i]);
    }
    float cnt = (float)(e - s);
    g_pooled[g * HID + f] = acc / fmaxf(cnt, 1.f);
}

// ---------------- out = pooled @ Wf + bf ----------------
__global__ void final_kernel(const float* __restrict__ Wf, const float* __restrict__ bfv,
                             float* __restrict__ out) {
    int g = blockIdx.x;
    int e = threadIdx.x;
    __shared__ float p[HID];
    for (int i = threadIdx.x; i < HID; i += EMB) p[i] = g_pooled[g * HID + i];
    __syncthreads();
    float acc = bfv[e];
#pragma unroll 4
    for (int k = 0; k < HID; ++k) acc += p[k] * Wf[k * EMB + e];
    out[g * EMB + e] = acc;
}

// ---------------- launch ----------------
extern "C" void kernel_launch(void* const* d_in, const int* in_sizes, int n_in,
                              void* d_out, int out_size) {
    const float* x   = (const float*)d_in[0];
    const int*   ei  = (const int*)d_in[1];
    const int* batch = (const int*)d_in[2];
    const float* Wp  = (const float*)d_in[3];
    const float* bp  = (const float*)d_in[4];
    const float* W1  = (const float*)d_in[5];
    const float* b1  = (const float*)d_in[6];
    const float* W2  = (const float*)d_in[7];
    const float* b2  = (const float*)d_in[8];
    const float* Wf  = (const float*)d_in[9];
    const float* bf  = (const float*)d_in[10];
    float* out = (float*)d_out;

    const int* src = ei;
    const int* dst = ei + N_EDGES;

    __nv_bfloat16 *wth, *wtl, *hh, *hl, *ah, *al, *zh, *zl;
    cudaGetSymbolAddress((void**)&wth, g_wth);
    cudaGetSymbolAddress((void**)&wtl, g_wtl);
    cudaGetSymbolAddress((void**)&hh, g_hh);
    cudaGetSymbolAddress((void**)&hl, g_hl);
    cudaGetSymbolAddress((void**)&ah, g_ah);
    cudaGetSymbolAddress((void**)&al, g_al);
    cudaGetSymbolAddress((void**)&zh, g_zh);
    cudaGetSymbolAddress((void**)&zl, g_zl);

    cudaFuncSetAttribute(gemm_mma, cudaFuncAttributeMaxDynamicSharedMemorySize, GSMEM);

    // weight transpose + hi/lo split
    wconv_kernel<<<dim3(HID / 32, HID / 32, 32), dim3(32, 8)>>>(W1, W2);

    // CSR build (fast scan)
    zero_fill<<<(N_NODES + 255) / 256, 256>>>();
    count_kernel<<<(N_EDGES + 255) / 256, 256>>>(dst);
    bsum_kernel<<<NB, 1024>>>();
    bscan_kernel<<<1, 128>>>();
    offs_kernel<<<NB, 1024>>>();
    fill_kernel<<<(N_EDGES + 255) / 256, 256>>>(src, dst);

    proj_kernel<<<N_NODES, HID>>>(x, Wp, bp);

    dim3 ggrid(HID / BN, (N_NODES + BM - 1) / BM);   // (6, 782)
    for (int l = 0; l < N_LAYERS; ++l) {
        gather_kernel<<<N_NODES, HID / 4>>>();
        gemm_mma<<<ggrid, 256, GSMEM>>>(ah, al, wth + (size_t)l * HSQ,
                                        wtl + (size_t)l * HSQ, b1 + l * HID, zh, zl);
        gemm_mma<<<ggrid, 256, GSMEM>>>(zh, zl, wth + (size_t)(16 + l) * HSQ,
                                        wtl + (size_t)(16 + l) * HSQ, b2 + l * HID, hh, hl);
    }

    find_starts<<<1, N_GRAPHS + 1>>>(batch);
    pool_kernel<<<dim3(N_GRAPHS, HID / 256), 256>>>();
    final_kernel<<<N_GRAPHS, EMB>>>(Wf, bf, out);
}